// round 1
// baseline (speedup 1.0000x reference)
#include <cuda_runtime.h>

// Problem constants (ShowAndTell GRU decoder)
#define BB 128        // batch
#define TT 31         // decode steps (T-1)
#define EE 300        // embed dim
#define HH 512        // hidden
#define VV 32000      // vocab
#define G3 1536       // 3*H
#define KSPLIT 8      // K-split for recurrent GEMM

// Scratch (static device globals; no allocation allowed)
__device__ float d_Hseq[32 * BB * HH];        // h_0 .. h_31   [t][b][h]
__device__ float d_GI[TT * BB * G3];          // input gates   [(t*B+b)][3H]
__device__ float d_GHpart[KSPLIT * BB * G3];  // split-K partials of h @ W_hh^T

// ---------- packed f32x2 helpers (FFMA2 path, PTX-only per SASS_QUICKREF) ----------
static __device__ __forceinline__ unsigned long long pk2(float a) {
    unsigned long long r;
    asm("mov.b64 %0, {%1, %1};" : "=l"(r) : "f"(a));
    return r;
}
static __device__ __forceinline__ void ffma2(unsigned long long &c,
                                             unsigned long long a,
                                             unsigned long long b) {
    asm("fma.rn.f32x2 %0, %1, %2, %0;" : "+l"(c) : "l"(a), "l"(b));
}
static __device__ __forceinline__ float2 up2(unsigned long long v) {
    float2 f;
    asm("mov.b64 {%0, %1}, %2;" : "=f"(f.x), "=f"(f.y) : "l"(v));
    return f;
}

// ---------------------------------------------------------------------------
// Kernel 1: hidden0 = relu(concat(g,t) @ W_feat + b_feat)   -> d_Hseq[0]
// grid (2, 128), block 256.  W_feat: [256, 512] row-major.
// ---------------------------------------------------------------------------
__global__ void k_feat(const float* __restrict__ g, const float* __restrict__ t,
                       const float* __restrict__ Wf, const float* __restrict__ bf) {
    __shared__ float sg[128], st[128];
    int b = blockIdx.y;
    int j = blockIdx.x * 256 + threadIdx.x;
    if (threadIdx.x < 128) {
        sg[threadIdx.x] = g[b * 128 + threadIdx.x];
        st[threadIdx.x] = t[b * 128 + threadIdx.x];
    }
    __syncthreads();
    float acc = bf[j];
#pragma unroll 4
    for (int k = 0; k < 128; k++) acc += sg[k] * Wf[k * HH + j];
#pragma unroll 4
    for (int k = 0; k < 128; k++) acc += st[k] * Wf[(128 + k) * HH + j];
    d_Hseq[b * HH + j] = fmaxf(acc, 0.f);
}

// ---------------------------------------------------------------------------
// Kernel 2: GI = X @ W_ih^T + b_ih (all timesteps, no recurrence)
// M = 31*128 rows (one t-tile per blockIdx.y), N = 1536, K = 300.
// lang_feat: [B, 32, 300]; W_ih: [1536, 300] (both K-contiguous -> NT GEMM).
// grid (12, 31), block 256, 128x128 tile, 8x8 micro via f32x2.
// ---------------------------------------------------------------------------
__global__ __launch_bounds__(256, 2) void k_gi(const float* __restrict__ lf,
                                               const float* __restrict__ Wih,
                                               const float* __restrict__ bih) {
    __shared__ float As[16][132];   // [k][b]
    __shared__ float Bs[16][132];   // [k][n]
    int tid = threadIdx.x;
    int tx = tid & 15, ty = tid >> 4;
    int n0 = blockIdx.x * 128;
    int ts = blockIdx.y;

    unsigned long long acc[8][4];
#pragma unroll
    for (int i = 0; i < 8; i++)
#pragma unroll
        for (int j = 0; j < 4; j++) acc[i][j] = 0ull;

    int lr = tid >> 2;          // 0..63
    int lk = (tid & 3) * 4;     // 0,4,8,12

    for (int k0 = 0; k0 < EE; k0 += 16) {
        bool kok = (k0 + lk) < EE;   // 300 % 4 == 0, so float4 all-or-nothing
#pragma unroll
        for (int p = 0; p < 2; p++) {
            int r = lr + p * 64;
            float4 v = make_float4(0.f, 0.f, 0.f, 0.f);
            float4 w = make_float4(0.f, 0.f, 0.f, 0.f);
            if (kok) {
                v = *(const float4*)&lf[(size_t)(r * 32 + ts) * EE + k0 + lk];   // x[b=r][t=ts]
                w = *(const float4*)&Wih[(size_t)(n0 + r) * EE + k0 + lk];
            }
            As[lk + 0][r] = v.x; As[lk + 1][r] = v.y; As[lk + 2][r] = v.z; As[lk + 3][r] = v.w;
            Bs[lk + 0][r] = w.x; Bs[lk + 1][r] = w.y; Bs[lk + 2][r] = w.z; Bs[lk + 3][r] = w.w;
        }
        __syncthreads();
#pragma unroll
        for (int k = 0; k < 16; k++) {
            float4 a0 = *(const float4*)&As[k][ty * 8];
            float4 a1 = *(const float4*)&As[k][ty * 8 + 4];
            ulonglong2 q0 = *(const ulonglong2*)&Bs[k][tx * 8];
            ulonglong2 q1 = *(const ulonglong2*)&Bs[k][tx * 8 + 4];
            unsigned long long b0 = q0.x, b1 = q0.y, b2 = q1.x, b3 = q1.y;
            float av[8] = {a0.x, a0.y, a0.z, a0.w, a1.x, a1.y, a1.z, a1.w};
#pragma unroll
            for (int i = 0; i < 8; i++) {
                unsigned long long ap = pk2(av[i]);
                ffma2(acc[i][0], ap, b0); ffma2(acc[i][1], ap, b1);
                ffma2(acc[i][2], ap, b2); ffma2(acc[i][3], ap, b3);
            }
        }
        __syncthreads();
    }

    int nb = n0 + tx * 8;
    float4 bi0 = *(const float4*)&bih[nb];
    float4 bi1 = *(const float4*)&bih[nb + 4];
#pragma unroll
    for (int i = 0; i < 8; i++) {
        int b = ty * 8 + i;
        float* o = &d_GI[(size_t)(ts * BB + b) * G3 + nb];
        float2 c0 = up2(acc[i][0]), c1 = up2(acc[i][1]);
        float2 c2 = up2(acc[i][2]), c3 = up2(acc[i][3]);
        float4 o0 = make_float4(c0.x + bi0.x, c0.y + bi0.y, c1.x + bi0.z, c1.y + bi0.w);
        float4 o1 = make_float4(c2.x + bi1.x, c2.y + bi1.y, c3.x + bi1.z, c3.y + bi1.w);
        *(float4*)o = o0;
        *(float4*)(o + 4) = o1;
    }
}

// ---------------------------------------------------------------------------
// Kernel 3a: split-K GEMM  GHpart[ks] = h_t @ W_hh^T (K range ks*64..+64)
// M=128, N=1536, K=512. grid (24, 8), block 256, tile 128x64, micro 8x4.
// ---------------------------------------------------------------------------
__global__ __launch_bounds__(256) void k_gh(int t, const float* __restrict__ Whh) {
    __shared__ float As[16][132];   // [k][b]
    __shared__ float Bs[16][68];    // [k][n]
    int tid = threadIdx.x;
    int tx = tid & 15, ty = tid >> 4;
    int n0 = blockIdx.x * 64;
    int kbase = blockIdx.y * 64;
    const float* hp = d_Hseq + (size_t)t * BB * HH;

    float acc[8][4];
#pragma unroll
    for (int i = 0; i < 8; i++)
#pragma unroll
        for (int j = 0; j < 4; j++) acc[i][j] = 0.f;

    int lr = tid >> 2, lk = (tid & 3) * 4;

    for (int kc = 0; kc < 64; kc += 16) {
        int k0 = kbase + kc;
#pragma unroll
        for (int p = 0; p < 2; p++) {
            int b = lr + p * 64;
            float4 v = *(const float4*)&hp[(size_t)b * HH + k0 + lk];
            As[lk + 0][b] = v.x; As[lk + 1][b] = v.y; As[lk + 2][b] = v.z; As[lk + 3][b] = v.w;
        }
        {
            float4 w = *(const float4*)&Whh[(size_t)(n0 + lr) * HH + k0 + lk];
            Bs[lk + 0][lr] = w.x; Bs[lk + 1][lr] = w.y; Bs[lk + 2][lr] = w.z; Bs[lk + 3][lr] = w.w;
        }
        __syncthreads();
#pragma unroll
        for (int k = 0; k < 16; k++) {
            float4 a0 = *(const float4*)&As[k][ty * 8];
            float4 a1 = *(const float4*)&As[k][ty * 8 + 4];
            float4 bv = *(const float4*)&Bs[k][tx * 4];
            float av[8] = {a0.x, a0.y, a0.z, a0.w, a1.x, a1.y, a1.z, a1.w};
#pragma unroll
            for (int i = 0; i < 8; i++) {
                acc[i][0] += av[i] * bv.x;
                acc[i][1] += av[i] * bv.y;
                acc[i][2] += av[i] * bv.z;
                acc[i][3] += av[i] * bv.w;
            }
        }
        __syncthreads();
    }
#pragma unroll
    for (int i = 0; i < 8; i++) {
        int b = ty * 8 + i;
        *(float4*)&d_GHpart[(size_t)(blockIdx.y * BB + b) * G3 + n0 + tx * 4] =
            make_float4(acc[i][0], acc[i][1], acc[i][2], acc[i][3]);
    }
}

// ---------------------------------------------------------------------------
// Kernel 3b: reduce split-K partials + GRU gate math -> d_Hseq[t+1]
// 65536 threads, one per (b, j).
// ---------------------------------------------------------------------------
__global__ void k_gate(int t, const float* __restrict__ bhh) {
    int idx = blockIdx.x * 256 + threadIdx.x;   // 0 .. 128*512-1
    int b = idx >> 9, j = idx & 511;

    float ghr = bhh[j], ghz = bhh[512 + j], ghn = bhh[1024 + j];
#pragma unroll
    for (int ks = 0; ks < KSPLIT; ks++) {
        const float* p = d_GHpart + (size_t)(ks * BB + b) * G3;
        ghr += p[j];
        ghz += p[512 + j];
        ghn += p[1024 + j];
    }
    const float* gi = d_GI + (size_t)(t * BB + b) * G3;
    float gir = gi[j], giz = gi[512 + j], gin = gi[1024 + j];

    float r = 1.f / (1.f + expf(-(gir + ghr)));
    float z = 1.f / (1.f + expf(-(giz + ghz)));
    float n = tanhf(gin + r * ghn);
    float hp = d_Hseq[(size_t)t * BB * HH + idx];
    d_Hseq[(size_t)(t + 1) * BB * HH + idx] = (1.f - z) * n + z * hp;
}

// ---------------------------------------------------------------------------
// Kernel 4: logits = Hseq[1..31] @ W_cls + b_cls  -> out [B, 31, V]
// M = 3968 (one t per blockIdx.y), N = 32000, K = 512.
// grid (250, 31), block 256, tile 128x128, micro 8x8 via f32x2 (FFMA2).
// W_cls: [512, 32000] row-major (N-contiguous).
// ---------------------------------------------------------------------------
__global__ __launch_bounds__(256, 2) void k_logits(const float* __restrict__ Wc,
                                                   const float* __restrict__ bc,
                                                   float* __restrict__ out) {
    __shared__ float As[16][132];   // [k][b] transposed
    __shared__ float Bs[16][128];   // [k][n] natural
    int tid = threadIdx.x;
    int tx = tid & 15, ty = tid >> 4;
    int n0 = blockIdx.x * 128;
    int ts = blockIdx.y;
    const float* Arow = d_Hseq + (size_t)(ts + 1) * BB * HH;   // h after step ts

    unsigned long long acc[8][4];
#pragma unroll
    for (int i = 0; i < 8; i++)
#pragma unroll
        for (int j = 0; j < 4; j++) acc[i][j] = 0ull;

    int ar = tid >> 2, ak = (tid & 3) * 4;   // A loader: row 0..63(+64), k quad
    int br = tid >> 5, bn = (tid & 31) * 4;  // B loader: k row 0..7(+8), n quad

    for (int k0 = 0; k0 < HH; k0 += 16) {
#pragma unroll
        for (int p = 0; p < 2; p++) {
            int b = ar + p * 64;
            float4 v = *(const float4*)&Arow[(size_t)b * HH + k0 + ak];
            As[ak + 0][b] = v.x; As[ak + 1][b] = v.y; As[ak + 2][b] = v.z; As[ak + 3][b] = v.w;
            int kr = br + p * 8;
            float4 w = *(const float4*)&Wc[(size_t)(k0 + kr) * VV + n0 + bn];
            *(float4*)&Bs[kr][bn] = w;
        }
        __syncthreads();
#pragma unroll
        for (int k = 0; k < 16; k++) {
            float4 a0 = *(const float4*)&As[k][ty * 8];
            float4 a1 = *(const float4*)&As[k][ty * 8 + 4];
            ulonglong2 q0 = *(const ulonglong2*)&Bs[k][tx * 8];
            ulonglong2 q1 = *(const ulonglong2*)&Bs[k][tx * 8 + 4];
            unsigned long long b0 = q0.x, b1 = q0.y, b2 = q1.x, b3 = q1.y;
            float av[8] = {a0.x, a0.y, a0.z, a0.w, a1.x, a1.y, a1.z, a1.w};
#pragma unroll
            for (int i = 0; i < 8; i++) {
                unsigned long long ap = pk2(av[i]);
                ffma2(acc[i][0], ap, b0); ffma2(acc[i][1], ap, b1);
                ffma2(acc[i][2], ap, b2); ffma2(acc[i][3], ap, b3);
            }
        }
        __syncthreads();
    }

    int nb = n0 + tx * 8;
    float4 bc0 = *(const float4*)&bc[nb];
    float4 bc1 = *(const float4*)&bc[nb + 4];
#pragma unroll
    for (int i = 0; i < 8; i++) {
        int b = ty * 8 + i;
        float* o = out + ((size_t)b * TT + ts) * VV + nb;   // out[b][ts][n]
        float2 c0 = up2(acc[i][0]), c1 = up2(acc[i][1]);
        float2 c2 = up2(acc[i][2]), c3 = up2(acc[i][3]);
        float4 o0 = make_float4(c0.x + bc0.x, c0.y + bc0.y, c1.x + bc0.z, c1.y + bc0.w);
        float4 o1 = make_float4(c2.x + bc1.x, c2.y + bc1.y, c3.x + bc1.z, c3.y + bc1.w);
        *(float4*)o = o0;
        *(float4*)(o + 4) = o1;
    }
}

// ---------------------------------------------------------------------------
extern "C" void kernel_launch(void* const* d_in, const int* in_sizes, int n_in,
                              void* d_out, int out_size) {
    const float* g_feat = (const float*)d_in[0];
    const float* t_feat = (const float*)d_in[1];
    const float* lang_feat = (const float*)d_in[2];
    // d_in[3] = lang_len (unused; T is static)
    const float* W_feat = (const float*)d_in[4];
    const float* b_feat = (const float*)d_in[5];
    const float* W_ih = (const float*)d_in[6];
    const float* W_hh = (const float*)d_in[7];
    const float* b_ih = (const float*)d_in[8];
    const float* b_hh = (const float*)d_in[9];
    const float* W_cls = (const float*)d_in[10];
    const float* b_cls = (const float*)d_in[11];
    float* out = (float*)d_out;

    // hidden0
    k_feat<<<dim3(2, BB), 256>>>(g_feat, t_feat, W_feat, b_feat);
    // all input gates at once (no recurrence)
    k_gi<<<dim3(G3 / 128, TT), 256>>>(lang_feat, W_ih, b_ih);
    // sequential GRU recurrence
    for (int t = 0; t < TT; t++) {
        k_gh<<<dim3(G3 / 64, KSPLIT), 256>>>(t, W_hh);
        k_gate<<<dim3(BB * HH / 256), 256>>>(t, b_hh);
    }
    // one big classifier GEMM over all timesteps
    k_logits<<<dim3(VV / 128, TT), 256>>>(W_cls, b_cls, out);
}

// round 6
// speedup vs baseline: 1.7830x; 1.7830x over previous
#include <cuda_runtime.h>
#include <cstdint>

// Problem constants (ShowAndTell GRU decoder)
#define BB 128        // batch
#define TT 31         // decode steps (T-1)
#define EE 300        // embed dim
#define HH 512        // hidden
#define VV 32000      // vocab
#define G3 1536       // 3*H
#define KSPLIT 8      // K-split for recurrent GEMM

// Scratch (static device globals; no allocation allowed)
__device__ float d_Hseq[32 * BB * HH];        // h_0 .. h_31   [t][b][h]
__device__ float d_GI[TT * BB * G3];          // input gates   [(t*B+b)][3H]
__device__ float d_GHpart[KSPLIT * BB * G3];  // split-K partials of h @ W_hh^T

// ---------- PTX helpers (base-target safe: sm_80+ features only) ----------
static __device__ __forceinline__ float tf32r(float x) {
    uint32_t u;
    asm("cvt.rna.tf32.f32 %0, %1;" : "=r"(u) : "f"(x));
    return __uint_as_float(u);
}
// m16n8k8 tf32 MMA (legacy HMMA path; supported on base sm_103 target)
static __device__ __forceinline__ void mma8(float* c, const uint32_t* a, const uint32_t* b) {
    asm volatile(
        "mma.sync.aligned.m16n8k8.row.col.f32.tf32.tf32.f32 "
        "{%0,%1,%2,%3}, {%4,%5,%6,%7}, {%8,%9}, {%0,%1,%2,%3};"
        : "+f"(c[0]), "+f"(c[1]), "+f"(c[2]), "+f"(c[3])
        : "r"(a[0]), "r"(a[1]), "r"(a[2]), "r"(a[3]), "r"(b[0]), "r"(b[1]));
}

// ---------- packed f32x2 helpers (FFMA2 path; proven on this toolchain) ----------
static __device__ __forceinline__ unsigned long long pk2(float a) {
    unsigned long long r;
    asm("mov.b64 %0, {%1, %1};" : "=l"(r) : "f"(a));
    return r;
}
static __device__ __forceinline__ void ffma2(unsigned long long &c,
                                             unsigned long long a,
                                             unsigned long long b) {
    asm("fma.rn.f32x2 %0, %1, %2, %0;" : "+l"(c) : "l"(a), "l"(b));
}
static __device__ __forceinline__ float2 up2(unsigned long long v) {
    float2 f;
    asm("mov.b64 {%0, %1}, %2;" : "=f"(f.x), "=f"(f.y) : "l"(v));
    return f;
}

// ---------------------------------------------------------------------------
// Kernel 1: hidden0 = relu(concat(g,t) @ W_feat + b_feat)   -> d_Hseq[0]
// ---------------------------------------------------------------------------
__global__ void k_feat(const float* __restrict__ g, const float* __restrict__ t,
                       const float* __restrict__ Wf, const float* __restrict__ bf) {
    __shared__ float sg[128], st[128];
    int b = blockIdx.y;
    int j = blockIdx.x * 256 + threadIdx.x;
    if (threadIdx.x < 128) {
        sg[threadIdx.x] = g[b * 128 + threadIdx.x];
        st[threadIdx.x] = t[b * 128 + threadIdx.x];
    }
    __syncthreads();
    float acc = bf[j];
#pragma unroll 4
    for (int k = 0; k < 128; k++) acc += sg[k] * Wf[k * HH + j];
#pragma unroll 4
    for (int k = 0; k < 128; k++) acc += st[k] * Wf[(128 + k) * HH + j];
    d_Hseq[b * HH + j] = fmaxf(acc, 0.f);
}

// ---------------------------------------------------------------------------
// Kernel 2: GI = X @ W_ih^T + b_ih (all timesteps, no recurrence)
// ---------------------------------------------------------------------------
__global__ __launch_bounds__(256, 2) void k_gi(const float* __restrict__ lf,
                                               const float* __restrict__ Wih,
                                               const float* __restrict__ bih) {
    __shared__ float As[16][132];
    __shared__ float Bs[16][132];
    int tid = threadIdx.x;
    int tx = tid & 15, ty = tid >> 4;
    int n0 = blockIdx.x * 128;
    int ts = blockIdx.y;

    unsigned long long acc[8][4];
#pragma unroll
    for (int i = 0; i < 8; i++)
#pragma unroll
        for (int j = 0; j < 4; j++) acc[i][j] = 0ull;

    int lr = tid >> 2;
    int lk = (tid & 3) * 4;

#pragma unroll 1
    for (int k0 = 0; k0 < EE; k0 += 16) {
        bool kok = (k0 + lk) < EE;
#pragma unroll
        for (int p = 0; p < 2; p++) {
            int r = lr + p * 64;
            float4 v = make_float4(0.f, 0.f, 0.f, 0.f);
            float4 w = make_float4(0.f, 0.f, 0.f, 0.f);
            if (kok) {
                v = *(const float4*)&lf[(size_t)(r * 32 + ts) * EE + k0 + lk];
                w = *(const float4*)&Wih[(size_t)(n0 + r) * EE + k0 + lk];
            }
            As[lk + 0][r] = v.x; As[lk + 1][r] = v.y; As[lk + 2][r] = v.z; As[lk + 3][r] = v.w;
            Bs[lk + 0][r] = w.x; Bs[lk + 1][r] = w.y; Bs[lk + 2][r] = w.z; Bs[lk + 3][r] = w.w;
        }
        __syncthreads();
#pragma unroll
        for (int k = 0; k < 16; k++) {
            float4 a0 = *(const float4*)&As[k][ty * 8];
            float4 a1 = *(const float4*)&As[k][ty * 8 + 4];
            ulonglong2 q0 = *(const ulonglong2*)&Bs[k][tx * 8];
            ulonglong2 q1 = *(const ulonglong2*)&Bs[k][tx * 8 + 4];
            unsigned long long b0 = q0.x, b1 = q0.y, b2 = q1.x, b3 = q1.y;
            float av[8] = {a0.x, a0.y, a0.z, a0.w, a1.x, a1.y, a1.z, a1.w};
#pragma unroll
            for (int i = 0; i < 8; i++) {
                unsigned long long ap = pk2(av[i]);
                ffma2(acc[i][0], ap, b0); ffma2(acc[i][1], ap, b1);
                ffma2(acc[i][2], ap, b2); ffma2(acc[i][3], ap, b3);
            }
        }
        __syncthreads();
    }

    int nb = n0 + tx * 8;
    float4 bi0 = *(const float4*)&bih[nb];
    float4 bi1 = *(const float4*)&bih[nb + 4];
#pragma unroll
    for (int i = 0; i < 8; i++) {
        int b = ty * 8 + i;
        float* o = &d_GI[(size_t)(ts * BB + b) * G3 + nb];
        float2 c0 = up2(acc[i][0]), c1 = up2(acc[i][1]);
        float2 c2 = up2(acc[i][2]), c3 = up2(acc[i][3]);
        float4 o0 = make_float4(c0.x + bi0.x, c0.y + bi0.y, c1.x + bi0.z, c1.y + bi0.w);
        float4 o1 = make_float4(c2.x + bi1.x, c2.y + bi1.y, c3.x + bi1.z, c3.y + bi1.w);
        *(float4*)o = o0;
        *(float4*)(o + 4) = o1;
    }
}

// ---------------------------------------------------------------------------
// Kernel 3a: split-K GEMM  GHpart[ks] = h_t @ W_hh^T
// ---------------------------------------------------------------------------
__global__ __launch_bounds__(256) void k_gh(int t, const float* __restrict__ Whh) {
    __shared__ float As[16][132];
    __shared__ float Bs[16][68];
    int tid = threadIdx.x;
    int tx = tid & 15, ty = tid >> 4;
    int n0 = blockIdx.x * 64;
    int kbase = blockIdx.y * 64;
    const float* hp = d_Hseq + (size_t)t * BB * HH;

    float acc[8][4];
#pragma unroll
    for (int i = 0; i < 8; i++)
#pragma unroll
        for (int j = 0; j < 4; j++) acc[i][j] = 0.f;

    int lr = tid >> 2, lk = (tid & 3) * 4;

#pragma unroll 1
    for (int kc = 0; kc < 64; kc += 16) {
        int k0 = kbase + kc;
#pragma unroll
        for (int p = 0; p < 2; p++) {
            int b = lr + p * 64;
            float4 v = *(const float4*)&hp[(size_t)b * HH + k0 + lk];
            As[lk + 0][b] = v.x; As[lk + 1][b] = v.y; As[lk + 2][b] = v.z; As[lk + 3][b] = v.w;
        }
        {
            float4 w = *(const float4*)&Whh[(size_t)(n0 + lr) * HH + k0 + lk];
            Bs[lk + 0][lr] = w.x; Bs[lk + 1][lr] = w.y; Bs[lk + 2][lr] = w.z; Bs[lk + 3][lr] = w.w;
        }
        __syncthreads();
#pragma unroll
        for (int k = 0; k < 16; k++) {
            float4 a0 = *(const float4*)&As[k][ty * 8];
            float4 a1 = *(const float4*)&As[k][ty * 8 + 4];
            float4 bv = *(const float4*)&Bs[k][tx * 4];
            float av[8] = {a0.x, a0.y, a0.z, a0.w, a1.x, a1.y, a1.z, a1.w};
#pragma unroll
            for (int i = 0; i < 8; i++) {
                acc[i][0] += av[i] * bv.x;
                acc[i][1] += av[i] * bv.y;
                acc[i][2] += av[i] * bv.z;
                acc[i][3] += av[i] * bv.w;
            }
        }
        __syncthreads();
    }
#pragma unroll
    for (int i = 0; i < 8; i++) {
        int b = ty * 8 + i;
        *(float4*)&d_GHpart[(size_t)(blockIdx.y * BB + b) * G3 + n0 + tx * 4] =
            make_float4(acc[i][0], acc[i][1], acc[i][2], acc[i][3]);
    }
}

// ---------------------------------------------------------------------------
// Kernel 3b: reduce split-K partials + GRU gate math -> d_Hseq[t+1]
// ---------------------------------------------------------------------------
__global__ void k_gate(int t, const float* __restrict__ bhh) {
    int idx = blockIdx.x * 256 + threadIdx.x;
    int b = idx >> 9, j = idx & 511;

    float ghr = bhh[j], ghz = bhh[512 + j], ghn = bhh[1024 + j];
#pragma unroll
    for (int ks = 0; ks < KSPLIT; ks++) {
        const float* p = d_GHpart + (size_t)(ks * BB + b) * G3;
        ghr += p[j];
        ghz += p[512 + j];
        ghn += p[1024 + j];
    }
    const float* gi = d_GI + (size_t)(t * BB + b) * G3;
    float gir = gi[j], giz = gi[512 + j], gin = gi[1024 + j];

    float r = 1.f / (1.f + expf(-(gir + ghr)));
    float z = 1.f / (1.f + expf(-(giz + ghz)));
    float n = tanhf(gin + r * ghn);
    float hp = d_Hseq[(size_t)t * BB * HH + idx];
    d_Hseq[(size_t)(t + 1) * BB * HH + idx] = (1.f - z) * n + z * hp;
}

// ---------------------------------------------------------------------------
// Kernel 4: tf32 mma.sync GEMM  out[b][ts][n] = Hseq[ts+1] @ W_cls + b_cls
// CTA tile 128x128, 256 threads (8 warps, warp grid 4m x 2n, warp tile 32x64).
// K=512 in 16 serial chunks of 32 (outer loop kept rolled: bounded code size).
// B = W_cls [512][32000] used DIRECTLY (col-frag reads Bs[k][n]); tf32 rna
// rounding applied during LDG->STS.
// grid (TT, 250): mt fast so 31 CTAs sharing a B tile are wave-adjacent (L2).
// ---------------------------------------------------------------------------
__global__ __launch_bounds__(256, 2) void k_mma(const float* __restrict__ Wc,
                                                const float* __restrict__ bcls,
                                                float* __restrict__ out) {
    __shared__ float As[128][36];    // [m][k], pad 4 -> conflict-free frags
    __shared__ float Bs[32][132];    // [k][n], pad 4 -> conflict-free frags
    int tid = threadIdx.x;
    int wid = tid >> 5, lane = tid & 31;
    int g = lane >> 2, tig = lane & 3;
    int mt = blockIdx.x, nt = blockIdx.y;
    int n0 = nt * 128;
    const float* Ab = d_Hseq + (size_t)(mt + 1) * BB * HH;   // h after step mt
    int wm = (wid & 3) * 32;        // warp M offset (4 warps along M)
    int wn = (wid >> 2) * 64;       // warp N offset (2 warps along N)

    float acc[2][8][4];             // [mi][nj][c]
#pragma unroll
    for (int mi = 0; mi < 2; mi++)
#pragma unroll
        for (int nj = 0; nj < 8; nj++)
#pragma unroll
            for (int q = 0; q < 4; q++) acc[mi][nj][q] = 0.f;

    // loaders
    int arow = tid >> 1, acolb = (tid & 1) * 16;     // A: 128 rows x 32 cols
    int brow = tid >> 3, bcolb = (tid & 7) * 4;      // B: 32 rows x 128 cols

#pragma unroll 1
    for (int c = 0; c < 16; c++) {
        int k0 = c * 32;
        __syncthreads();   // previous chunk's consumers done before overwrite
#pragma unroll
        for (int i = 0; i < 4; i++) {
            float4 v = *(const float4*)&Ab[(size_t)arow * HH + k0 + acolb + i * 4];
            v.x = tf32r(v.x); v.y = tf32r(v.y); v.z = tf32r(v.z); v.w = tf32r(v.w);
            *(float4*)&As[arow][acolb + i * 4] = v;
        }
#pragma unroll
        for (int i = 0; i < 4; i++) {
            float4 v = *(const float4*)&Wc[(size_t)(k0 + brow) * VV + n0 + bcolb + 32 * i];
            v.x = tf32r(v.x); v.y = tf32r(v.y); v.z = tf32r(v.z); v.w = tf32r(v.w);
            *(float4*)&Bs[brow][bcolb + 32 * i] = v;
        }
        __syncthreads();

#pragma unroll
        for (int kk = 0; kk < 32; kk += 8) {
            uint32_t af[2][4];
#pragma unroll
            for (int mi = 0; mi < 2; mi++) {
                int m = wm + mi * 16;
                af[mi][0] = __float_as_uint(As[m + g][kk + tig]);
                af[mi][1] = __float_as_uint(As[m + g + 8][kk + tig]);
                af[mi][2] = __float_as_uint(As[m + g][kk + tig + 4]);
                af[mi][3] = __float_as_uint(As[m + g + 8][kk + tig + 4]);
            }
            uint32_t bf[8][2];
#pragma unroll
            for (int nj = 0; nj < 8; nj++) {
                int n = wn + nj * 8 + g;
                bf[nj][0] = __float_as_uint(Bs[kk + tig][n]);
                bf[nj][1] = __float_as_uint(Bs[kk + tig + 4][n]);
            }
#pragma unroll
            for (int mi = 0; mi < 2; mi++)
#pragma unroll
                for (int nj = 0; nj < 8; nj++)
                    mma8(acc[mi][nj], af[mi], bf[nj]);
        }
    }

    // epilogue: C[m][n] -> out[(m)*TT + mt][n0+n], + bias
#pragma unroll
    for (int mi = 0; mi < 2; mi++) {
        int m = wm + mi * 16;
        int r0 = m + g, r1 = m + g + 8;
        float* o0 = out + ((size_t)r0 * TT + mt) * VV + n0;
        float* o1 = out + ((size_t)r1 * TT + mt) * VV + n0;
#pragma unroll
        for (int nj = 0; nj < 8; nj++) {
            int n = wn + nj * 8 + 2 * tig;
            float2 bv = *(const float2*)&bcls[n0 + n];
            float2 v0 = make_float2(acc[mi][nj][0] + bv.x, acc[mi][nj][1] + bv.y);
            float2 v1 = make_float2(acc[mi][nj][2] + bv.x, acc[mi][nj][3] + bv.y);
            *(float2*)&o0[n] = v0;
            *(float2*)&o1[n] = v1;
        }
    }
}

// ---------------------------------------------------------------------------
extern "C" void kernel_launch(void* const* d_in, const int* in_sizes, int n_in,
                              void* d_out, int out_size) {
    const float* g_feat = (const float*)d_in[0];
    const float* t_feat = (const float*)d_in[1];
    const float* lang_feat = (const float*)d_in[2];
    // d_in[3] = lang_len (unused; T is static)
    const float* W_feat = (const float*)d_in[4];
    const float* b_feat = (const float*)d_in[5];
    const float* W_ih = (const float*)d_in[6];
    const float* W_hh = (const float*)d_in[7];
    const float* b_ih = (const float*)d_in[8];
    const float* b_hh = (const float*)d_in[9];
    const float* W_cls = (const float*)d_in[10];
    const float* b_cls = (const float*)d_in[11];
    float* out = (float*)d_out;

    // hidden0
    k_feat<<<dim3(2, BB), 256>>>(g_feat, t_feat, W_feat, b_feat);
    // all input gates at once (no recurrence)
    k_gi<<<dim3(G3 / 128, TT), 256>>>(lang_feat, W_ih, b_ih);
    // sequential GRU recurrence
    for (int t = 0; t < TT; t++) {
        k_gh<<<dim3(G3 / 64, KSPLIT), 256>>>(t, W_hh);
        k_gate<<<dim3(BB * HH / 256), 256>>>(t, b_hh);
    }
    // tf32 tensor-core classifier GEMM over all timesteps (mt fast for L2 reuse)
    k_mma<<<dim3(TT, VV / 128), 256>>>(W_cls, b_cls, out);
}

// round 8
// speedup vs baseline: 2.0370x; 1.1424x over previous
#include <cuda_runtime.h>
#include <cstdint>

// Problem constants (ShowAndTell GRU decoder)
#define BB 128        // batch
#define TT 31         // decode steps (T-1)
#define EE 300        // embed dim
#define HH 512        // hidden
#define VV 32000      // vocab
#define G3 1536       // 3*H
#define KSPLIT 8      // K-split for recurrent GEMM

// Scratch (static device globals; no allocation allowed)
__device__ float d_Hseq[32 * BB * HH];        // h_0 .. h_31   [t][b][h]
__device__ float d_GI[TT * BB * G3];          // input gates   [(t*B+b)][3H]
__device__ float d_GHpart[KSPLIT * BB * G3];  // split-K partials of h @ W_hh^T

// ---------- PTX helpers (base-target safe: sm_80+ features only) ----------
static __device__ __forceinline__ float tf32r(float x) {
    uint32_t u;
    asm("cvt.rna.tf32.f32 %0, %1;" : "=r"(u) : "f"(x));
    return __uint_as_float(u);
}
// m16n8k8 tf32 MMA (legacy HMMA path; supported on base sm_103 target)
static __device__ __forceinline__ void mma8(float* c, const uint32_t* a, const uint32_t* b) {
    asm volatile(
        "mma.sync.aligned.m16n8k8.row.col.f32.tf32.tf32.f32 "
        "{%0,%1,%2,%3}, {%4,%5,%6,%7}, {%8,%9}, {%0,%1,%2,%3};"
        : "+f"(c[0]), "+f"(c[1]), "+f"(c[2]), "+f"(c[3])
        : "r"(a[0]), "r"(a[1]), "r"(a[2]), "r"(a[3]), "r"(b[0]), "r"(b[1]));
}

// ---------- packed f32x2 helpers (FFMA2 path; proven on this toolchain) ----------
static __device__ __forceinline__ unsigned long long pk2(float a) {
    unsigned long long r;
    asm("mov.b64 %0, {%1, %1};" : "=l"(r) : "f"(a));
    return r;
}
static __device__ __forceinline__ void ffma2(unsigned long long &c,
                                             unsigned long long a,
                                             unsigned long long b) {
    asm("fma.rn.f32x2 %0, %1, %2, %0;" : "+l"(c) : "l"(a), "l"(b));
}
static __device__ __forceinline__ float2 up2(unsigned long long v) {
    float2 f;
    asm("mov.b64 {%0, %1}, %2;" : "=f"(f.x), "=f"(f.y) : "l"(v));
    return f;
}

// ---------------------------------------------------------------------------
// Kernel 1: hidden0 = relu(concat(g,t) @ W_feat + b_feat)   -> d_Hseq[0]
// ---------------------------------------------------------------------------
__global__ void k_feat(const float* __restrict__ g, const float* __restrict__ t,
                       const float* __restrict__ Wf, const float* __restrict__ bf) {
    __shared__ float sg[128], st[128];
    int b = blockIdx.y;
    int j = blockIdx.x * 256 + threadIdx.x;
    if (threadIdx.x < 128) {
        sg[threadIdx.x] = g[b * 128 + threadIdx.x];
        st[threadIdx.x] = t[b * 128 + threadIdx.x];
    }
    __syncthreads();
    float acc = bf[j];
#pragma unroll 4
    for (int k = 0; k < 128; k++) acc += sg[k] * Wf[k * HH + j];
#pragma unroll 4
    for (int k = 0; k < 128; k++) acc += st[k] * Wf[(128 + k) * HH + j];
    d_Hseq[b * HH + j] = fmaxf(acc, 0.f);
}

// ---------------------------------------------------------------------------
// Kernel 2: GI = X @ W_ih^T + b_ih (all timesteps, no recurrence)
// ---------------------------------------------------------------------------
__global__ __launch_bounds__(256, 2) void k_gi(const float* __restrict__ lf,
                                               const float* __restrict__ Wih,
                                               const float* __restrict__ bih) {
    __shared__ float As[16][132];
    __shared__ float Bs[16][132];
    int tid = threadIdx.x;
    int tx = tid & 15, ty = tid >> 4;
    int n0 = blockIdx.x * 128;
    int ts = blockIdx.y;

    unsigned long long acc[8][4];
#pragma unroll
    for (int i = 0; i < 8; i++)
#pragma unroll
        for (int j = 0; j < 4; j++) acc[i][j] = 0ull;

    int lr = tid >> 2;
    int lk = (tid & 3) * 4;

#pragma unroll 1
    for (int k0 = 0; k0 < EE; k0 += 16) {
        bool kok = (k0 + lk) < EE;
#pragma unroll
        for (int p = 0; p < 2; p++) {
            int r = lr + p * 64;
            float4 v = make_float4(0.f, 0.f, 0.f, 0.f);
            float4 w = make_float4(0.f, 0.f, 0.f, 0.f);
            if (kok) {
                v = *(const float4*)&lf[(size_t)(r * 32 + ts) * EE + k0 + lk];
                w = *(const float4*)&Wih[(size_t)(n0 + r) * EE + k0 + lk];
            }
            As[lk + 0][r] = v.x; As[lk + 1][r] = v.y; As[lk + 2][r] = v.z; As[lk + 3][r] = v.w;
            Bs[lk + 0][r] = w.x; Bs[lk + 1][r] = w.y; Bs[lk + 2][r] = w.z; Bs[lk + 3][r] = w.w;
        }
        __syncthreads();
#pragma unroll
        for (int k = 0; k < 16; k++) {
            float4 a0 = *(const float4*)&As[k][ty * 8];
            float4 a1 = *(const float4*)&As[k][ty * 8 + 4];
            ulonglong2 q0 = *(const ulonglong2*)&Bs[k][tx * 8];
            ulonglong2 q1 = *(const ulonglong2*)&Bs[k][tx * 8 + 4];
            unsigned long long b0 = q0.x, b1 = q0.y, b2 = q1.x, b3 = q1.y;
            float av[8] = {a0.x, a0.y, a0.z, a0.w, a1.x, a1.y, a1.z, a1.w};
#pragma unroll
            for (int i = 0; i < 8; i++) {
                unsigned long long ap = pk2(av[i]);
                ffma2(acc[i][0], ap, b0); ffma2(acc[i][1], ap, b1);
                ffma2(acc[i][2], ap, b2); ffma2(acc[i][3], ap, b3);
            }
        }
        __syncthreads();
    }

    int nb = n0 + tx * 8;
    float4 bi0 = *(const float4*)&bih[nb];
    float4 bi1 = *(const float4*)&bih[nb + 4];
#pragma unroll
    for (int i = 0; i < 8; i++) {
        int b = ty * 8 + i;
        float* o = &d_GI[(size_t)(ts * BB + b) * G3 + nb];
        float2 c0 = up2(acc[i][0]), c1 = up2(acc[i][1]);
        float2 c2 = up2(acc[i][2]), c3 = up2(acc[i][3]);
        float4 o0 = make_float4(c0.x + bi0.x, c0.y + bi0.y, c1.x + bi0.z, c1.y + bi0.w);
        float4 o1 = make_float4(c2.x + bi1.x, c2.y + bi1.y, c3.x + bi1.z, c3.y + bi1.w);
        *(float4*)o = o0;
        *(float4*)(o + 4) = o1;
    }
}

// ---------------------------------------------------------------------------
// Kernel 3a: split-K GEMM  GHpart[ks] = h_t @ W_hh^T
// ---------------------------------------------------------------------------
__global__ __launch_bounds__(256) void k_gh(int t, const float* __restrict__ Whh) {
    __shared__ float As[16][132];
    __shared__ float Bs[16][68];
    int tid = threadIdx.x;
    int tx = tid & 15, ty = tid >> 4;
    int n0 = blockIdx.x * 64;
    int kbase = blockIdx.y * 64;
    const float* hp = d_Hseq + (size_t)t * BB * HH;

    float acc[8][4];
#pragma unroll
    for (int i = 0; i < 8; i++)
#pragma unroll
        for (int j = 0; j < 4; j++) acc[i][j] = 0.f;

    int lr = tid >> 2, lk = (tid & 3) * 4;

#pragma unroll 1
    for (int kc = 0; kc < 64; kc += 16) {
        int k0 = kbase + kc;
#pragma unroll
        for (int p = 0; p < 2; p++) {
            int b = lr + p * 64;
            float4 v = *(const float4*)&hp[(size_t)b * HH + k0 + lk];
            As[lk + 0][b] = v.x; As[lk + 1][b] = v.y; As[lk + 2][b] = v.z; As[lk + 3][b] = v.w;
        }
        {
            float4 w = *(const float4*)&Whh[(size_t)(n0 + lr) * HH + k0 + lk];
            Bs[lk + 0][lr] = w.x; Bs[lk + 1][lr] = w.y; Bs[lk + 2][lr] = w.z; Bs[lk + 3][lr] = w.w;
        }
        __syncthreads();
#pragma unroll
        for (int k = 0; k < 16; k++) {
            float4 a0 = *(const float4*)&As[k][ty * 8];
            float4 a1 = *(const float4*)&As[k][ty * 8 + 4];
            float4 bv = *(const float4*)&Bs[k][tx * 4];
            float av[8] = {a0.x, a0.y, a0.z, a0.w, a1.x, a1.y, a1.z, a1.w};
#pragma unroll
            for (int i = 0; i < 8; i++) {
                acc[i][0] += av[i] * bv.x;
                acc[i][1] += av[i] * bv.y;
                acc[i][2] += av[i] * bv.z;
                acc[i][3] += av[i] * bv.w;
            }
        }
        __syncthreads();
    }
#pragma unroll
    for (int i = 0; i < 8; i++) {
        int b = ty * 8 + i;
        *(float4*)&d_GHpart[(size_t)(blockIdx.y * BB + b) * G3 + n0 + tx * 4] =
            make_float4(acc[i][0], acc[i][1], acc[i][2], acc[i][3]);
    }
}

// ---------------------------------------------------------------------------
// Kernel 3b: reduce split-K partials + GRU gate math -> d_Hseq[t+1]
// ---------------------------------------------------------------------------
__global__ void k_gate(int t, const float* __restrict__ bhh) {
    int idx = blockIdx.x * 256 + threadIdx.x;
    int b = idx >> 9, j = idx & 511;

    float ghr = bhh[j], ghz = bhh[512 + j], ghn = bhh[1024 + j];
#pragma unroll
    for (int ks = 0; ks < KSPLIT; ks++) {
        const float* p = d_GHpart + (size_t)(ks * BB + b) * G3;
        ghr += p[j];
        ghz += p[512 + j];
        ghn += p[1024 + j];
    }
    const float* gi = d_GI + (size_t)(t * BB + b) * G3;
    float gir = gi[j], giz = gi[512 + j], gin = gi[1024 + j];

    float r = 1.f / (1.f + expf(-(gir + ghr)));
    float z = 1.f / (1.f + expf(-(giz + ghz)));
    float n = tanhf(gin + r * ghn);
    float hp = d_Hseq[(size_t)t * BB * HH + idx];
    d_Hseq[(size_t)(t + 1) * BB * HH + idx] = (1.f - z) * n + z * hp;
}

// ---------------------------------------------------------------------------
// Kernel 4: tf32 mma.sync GEMM  out[b][ts][n] = Hseq[ts+1] @ W_cls + b_cls
// CTA tile 128x128, 256 threads (8 warps, warp grid 4m x 2n, warp tile 32x64).
// K=512 in 16 serial chunks of 32 with REGISTER double-buffer prefetch of the
// next chunk's A/B (hides L2 latency under LDS+MMA compute).
// Bs padded to 136 (mod 32 == 8) -> col-fragment reads bank = 8*tig + g,
// a perfect 32-bank spread (132 gave 2-way conflicts on every B LDS).
// grid (TT, 250): mt fast so 31 CTAs sharing a B tile are wave-adjacent (L2).
// ---------------------------------------------------------------------------
__global__ __launch_bounds__(256, 2) void k_mma(const float* __restrict__ Wc,
                                                const float* __restrict__ bcls,
                                                float* __restrict__ out) {
    __shared__ float As[128][36];    // [m][k], pad 4 -> conflict-free frags
    __shared__ float Bs[32][136];    // [k][n], pad 8 -> conflict-free frags
    int tid = threadIdx.x;
    int wid = tid >> 5, lane = tid & 31;
    int g = lane >> 2, tig = lane & 3;
    int mt = blockIdx.x, nt = blockIdx.y;
    int n0 = nt * 128;
    const float* Ab = d_Hseq + (size_t)(mt + 1) * BB * HH;   // h after step mt
    int wm = (wid & 3) * 32;        // warp M offset (4 warps along M)
    int wn = (wid >> 2) * 64;       // warp N offset (2 warps along N)

    float acc[2][8][4];             // [mi][nj][c]
#pragma unroll
    for (int mi = 0; mi < 2; mi++)
#pragma unroll
        for (int nj = 0; nj < 8; nj++)
#pragma unroll
            for (int q = 0; q < 4; q++) acc[mi][nj][q] = 0.f;

    // loaders
    int arow = tid >> 1, acolb = (tid & 1) * 16;     // A: 128 rows x 32 cols
    int brow = tid >> 3, bcolb = (tid & 7) * 4;      // B: 32 rows x 128 cols
    const float* Aptr = &Ab[(size_t)arow * HH + acolb];
    const float* Bptr = &Wc[(size_t)brow * VV + n0 + bcolb];

    // prefetch chunk 0 into registers
    float4 pa[4], pb[4];
#pragma unroll
    for (int i = 0; i < 4; i++) pa[i] = *(const float4*)&Aptr[i * 4];
#pragma unroll
    for (int i = 0; i < 4; i++) pb[i] = *(const float4*)&Bptr[32 * i];

#pragma unroll 1
    for (int c = 0; c < 16; c++) {
        __syncthreads();   // previous chunk's consumers done before overwrite
#pragma unroll
        for (int i = 0; i < 4; i++) {
            float4 v = pa[i];
            v.x = tf32r(v.x); v.y = tf32r(v.y); v.z = tf32r(v.z); v.w = tf32r(v.w);
            *(float4*)&As[arow][acolb + i * 4] = v;
        }
#pragma unroll
        for (int i = 0; i < 4; i++) {
            float4 v = pb[i];
            v.x = tf32r(v.x); v.y = tf32r(v.y); v.z = tf32r(v.z); v.w = tf32r(v.w);
            *(float4*)&Bs[brow][bcolb + 32 * i] = v;
        }
        __syncthreads();

        // issue next chunk's global loads; they complete under the compute below
        if (c < 15) {
            int k1 = (c + 1) * 32;
#pragma unroll
            for (int i = 0; i < 4; i++) pa[i] = *(const float4*)&Aptr[k1 + i * 4];
#pragma unroll
            for (int i = 0; i < 4; i++) pb[i] = *(const float4*)&Bptr[(size_t)k1 * VV + 32 * i];
        }

#pragma unroll
        for (int kk = 0; kk < 32; kk += 8) {
            uint32_t af[2][4];
#pragma unroll
            for (int mi = 0; mi < 2; mi++) {
                int m = wm + mi * 16;
                af[mi][0] = __float_as_uint(As[m + g][kk + tig]);
                af[mi][1] = __float_as_uint(As[m + g + 8][kk + tig]);
                af[mi][2] = __float_as_uint(As[m + g][kk + tig + 4]);
                af[mi][3] = __float_as_uint(As[m + g + 8][kk + tig + 4]);
            }
            uint32_t bf[8][2];
#pragma unroll
            for (int nj = 0; nj < 8; nj++) {
                int n = wn + nj * 8 + g;
                bf[nj][0] = __float_as_uint(Bs[kk + tig][n]);
                bf[nj][1] = __float_as_uint(Bs[kk + tig + 4][n]);
            }
#pragma unroll
            for (int mi = 0; mi < 2; mi++)
#pragma unroll
                for (int nj = 0; nj < 8; nj++)
                    mma8(acc[mi][nj], af[mi], bf[nj]);
        }
    }

    // epilogue: C[m][n] -> out[(m)*TT + mt][n0+n], + bias
#pragma unroll
    for (int mi = 0; mi < 2; mi++) {
        int m = wm + mi * 16;
        int r0 = m + g, r1 = m + g + 8;
        float* o0 = out + ((size_t)r0 * TT + mt) * VV + n0;
        float* o1 = out + ((size_t)r1 * TT + mt) * VV + n0;
#pragma unroll
        for (int nj = 0; nj < 8; nj++) {
            int n = wn + nj * 8 + 2 * tig;
            float2 bv = *(const float2*)&bcls[n0 + n];
            float2 v0 = make_float2(acc[mi][nj][0] + bv.x, acc[mi][nj][1] + bv.y);
            float2 v1 = make_float2(acc[mi][nj][2] + bv.x, acc[mi][nj][3] + bv.y);
            *(float2*)&o0[n] = v0;
            *(float2*)&o1[n] = v1;
        }
    }
}

// ---------------------------------------------------------------------------
extern "C" void kernel_launch(void* const* d_in, const int* in_sizes, int n_in,
                              void* d_out, int out_size) {
    const float* g_feat = (const float*)d_in[0];
    const float* t_feat = (const float*)d_in[1];
    const float* lang_feat = (const float*)d_in[2];
    // d_in[3] = lang_len (unused; T is static)
    const float* W_feat = (const float*)d_in[4];
    const float* b_feat = (const float*)d_in[5];
    const float* W_ih = (const float*)d_in[6];
    const float* W_hh = (const float*)d_in[7];
    const float* b_ih = (const float*)d_in[8];
    const float* b_hh = (const float*)d_in[9];
    const float* W_cls = (const float*)d_in[10];
    const float* b_cls = (const float*)d_in[11];
    float* out = (float*)d_out;

    // hidden0
    k_feat<<<dim3(2, BB), 256>>>(g_feat, t_feat, W_feat, b_feat);
    // all input gates at once (no recurrence)
    k_gi<<<dim3(G3 / 128, TT), 256>>>(lang_feat, W_ih, b_ih);
    // sequential GRU recurrence
    for (int t = 0; t < TT; t++) {
        k_gh<<<dim3(G3 / 64, KSPLIT), 256>>>(t, W_hh);
        k_gate<<<dim3(BB * HH / 256), 256>>>(t, b_hh);
    }
    // tf32 tensor-core classifier GEMM over all timesteps (mt fast for L2 reuse)
    k_mma<<<dim3(TT, VV / 128), 256>>>(W_cls, b_cls, out);
}